// round 7
// baseline (speedup 1.0000x reference)
#include <cuda_runtime.h>
#include <cstdint>

#define N_PARTICLES 131072
#define N_BEAMS     90
#define MAP_HW      800
#define N_TOTAL     (N_PARTICLES * N_BEAMS)
#define MAX_RANGE_PX 150.0f
#define OCC_THR     0.35f

// fp32(pi/180), identical to jnp.deg2rad's fp32 constant
#define DEG2RAD 0.017453292519943295f
// fp32(1/10): XLA algebraic simplifier rewrites x/10 -> x * (1/10)
#define INV10 0.1f

__global__ void __launch_bounds__(256)
raycast_kernel(const float* __restrict__ X,          // [N_PARTICLES, 3]
               const float* __restrict__ occ_map,    // [800, 800]
               float* __restrict__ out)              // [N_PARTICLES, 90]
{
    int idx = blockIdx.x * blockDim.x + threadIdx.x;
    if (idx >= N_TOTAL) return;

    int p = idx / N_BEAMS;
    int b = idx - p * N_BEAMS;

    // 90 consecutive threads read the same particle -> L1 broadcast
    float xb  = X[p * 3 + 0];
    float yb  = X[p * 3 + 1];
    float yaw = X[p * 3 + 2];

    // libdevice-equivalent trig (established bit-identical to correctly
    // rounded across R3/R4/R6).
    float cy = cosf(yaw);
    float sy = sinf(yaw);

    // Eager XLA ops, one rounding each (no contraction across ops), but
    // division by constant is canonicalized to multiply-by-reciprocal:
    //   xl = fp32( (xb + fp32(25*cy)) * fp32(0.1) )
    float xl = __fmul_rn(__fadd_rn(xb, __fmul_rn(25.0f, cy)), INV10);
    float yl = __fmul_rn(__fadd_rn(yb, __fmul_rn(25.0f, sy)), INV10);

    // ang = fp32(deg * pi/180) + yaw : two separate eager ops
    float ang_deg = (float)(-90 + 2 * b);
    float ang = __fadd_rn(__fmul_rn(ang_deg, DEG2RAD), yaw);
    float ca = cosf(ang);
    float sa = sinf(ang);

    // lax.scan body is one fused XLA:GPU computation (FPOpFusion::Fast):
    // xl + cos_a*r contracts to fma.rn. First occ>thr step == the min over
    // all steps, so early exit is exact.
    float hit = MAX_RANGE_PX;
    for (int r = 0; r <= 150; r++) {
        float rf = (float)r;
        float xp = __fmaf_rn(ca, rf, xl);
        float yp = __fmaf_rn(sa, rf, yl);
        // round half-to-even (jnp.round) then clip to [0, 799]
        float xr = fminf(fmaxf(rintf(xp), 0.0f), (float)(MAP_HW - 1));
        float yr = fminf(fmaxf(rintf(yp), 0.0f), (float)(MAP_HW - 1));
        int xi = (int)xr;
        int yi = (int)yr;
        float occ = __ldg(&occ_map[yi * MAP_HW + xi]);
        if (occ > OCC_THR) { hit = rf; break; }
    }

    out[idx] = hit;
}

extern "C" void kernel_launch(void* const* d_in, const int* in_sizes, int n_in,
                              void* d_out, int out_size)
{
    const float* X       = (const float*)d_in[0];   // X_t1 [131072, 3]
    const float* occ_map = (const float*)d_in[1];   // occupancy_map [800, 800]
    float* out           = (float*)d_out;           // [131072, 90]

    const int threads = 256;
    const int blocks  = (N_TOTAL + threads - 1) / threads;
    raycast_kernel<<<blocks, threads>>>(X, occ_map, out);
}

// round 8
// speedup vs baseline: 1.2563x; 1.2563x over previous
#include <cuda_runtime.h>
#include <cstdint>

#define N_PARTICLES 131072
#define N_BEAMS     90
#define MAP_HW      800
#define N_TOTAL     (N_PARTICLES * N_BEAMS)
#define MAX_RANGE_PX 150.0f
#define OCC_THR     0.35f

// fp32(pi/180), identical to jnp.deg2rad's fp32 constant
#define DEG2RAD 0.017453292519943295f
// XLA algebraic simplifier rewrites x/10 -> x * fp32(0.1)
#define INV10 0.1f

// Per-particle precomputed state: {x_laser, y_laser, yaw, unused}
__device__ float4 g_part[N_PARTICLES];

// ---------------------------------------------------------------------------
// Kernel 1: per-particle prologue (1/90th of the threads).
// Bit-identical to the eager-JAX prologue: separate mul/add roundings,
// reciprocal-multiply for /10, libdevice cosf/sinf.
// ---------------------------------------------------------------------------
__global__ void __launch_bounds__(256)
particle_prep_kernel(const float* __restrict__ X)   // [N_PARTICLES, 3]
{
    int p = blockIdx.x * blockDim.x + threadIdx.x;
    if (p >= N_PARTICLES) return;

    float xb  = X[p * 3 + 0];
    float yb  = X[p * 3 + 1];
    float yaw = X[p * 3 + 2];

    float cy = cosf(yaw);
    float sy = sinf(yaw);

    float xl = __fmul_rn(__fadd_rn(xb, __fmul_rn(25.0f, cy)), INV10);
    float yl = __fmul_rn(__fadd_rn(yb, __fmul_rn(25.0f, sy)), INV10);

    g_part[p] = make_float4(xl, yl, yaw, 0.0f);
}

// ---------------------------------------------------------------------------
// Kernel 2: one thread per (particle, beam) ray.
// ---------------------------------------------------------------------------
__global__ void __launch_bounds__(256)
raycast_kernel(const float* __restrict__ occ_map,   // [800, 800]
               float* __restrict__ out)             // [N_PARTICLES, 90]
{
    int idx = blockIdx.x * blockDim.x + threadIdx.x;
    if (idx >= N_TOTAL) return;

    int p = idx / N_BEAMS;          // magic-multiply, no real division
    int b = idx - p * N_BEAMS;

    // One LDG.128, broadcast across the 90 threads of this particle.
    float4 s = g_part[p];
    float xl  = s.x;
    float yl  = s.y;
    float yaw = s.z;

    // ang = fp32(deg * pi/180) + yaw : two separate eager-op roundings
    float ang_deg = (float)(-90 + 2 * b);
    float ang = __fadd_rn(__fmul_rn(ang_deg, DEG2RAD), yaw);
    float ca = cosf(ang);
    float sa = sinf(ang);

    // scan body fused by XLA:GPU (FPOpFusion::Fast) -> fma.rn contraction.
    // First step with occ > thr == min over all steps -> early exit exact.
    float hit = MAX_RANGE_PX;
    for (int r = 0; r <= 150; r++) {
        float rf = (float)r;
        float xp = __fmaf_rn(ca, rf, xl);
        float yp = __fmaf_rn(sa, rf, yl);
        // round-half-even directly to int (== jnp.round then astype(int32)
        // for our bounded, non-NaN range), clamp in integer domain
        // (== float clip to [0,799] for integral values).
        int xi = min(max(__float2int_rn(xp), 0), MAP_HW - 1);
        int yi = min(max(__float2int_rn(yp), 0), MAP_HW - 1);
        float occ = __ldg(&occ_map[yi * MAP_HW + xi]);
        if (occ > OCC_THR) { hit = rf; break; }
    }

    out[idx] = hit;
}

extern "C" void kernel_launch(void* const* d_in, const int* in_sizes, int n_in,
                              void* d_out, int out_size)
{
    const float* X       = (const float*)d_in[0];   // X_t1 [131072, 3]
    const float* occ_map = (const float*)d_in[1];   // occupancy_map [800, 800]
    float* out           = (float*)d_out;           // [131072, 90]

    const int threads = 256;

    particle_prep_kernel<<<(N_PARTICLES + threads - 1) / threads, threads>>>(X);

    raycast_kernel<<<(N_TOTAL + threads - 1) / threads, threads>>>(occ_map, out);
}